// round 2
// baseline (speedup 1.0000x reference)
#include <cuda_runtime.h>
#include <cstdint>

#define POOL 7
#define NUM_ROIS 512
#define IMG_H 128
#define IMG_W 128
#define CH 1024

// 2 cells per 256-thread block: threads 0-127 -> cell0, 128-255 -> cell1.
// Each thread handles 8 channels (2 x float4 per corner) => 8 outstanding loads.
__global__ __launch_bounds__(256, 8)
void roi_pool_kernel(const float* __restrict__ img,
                     const int* __restrict__ rois,
                     float* __restrict__ out) {
    const int half = threadIdx.x >> 7;        // 0 or 1
    const int lane = threadIdx.x & 127;       // 0..127
    const int cell = blockIdx.x * 2 + half;   // roi*49 + py*7 + px

    const int roi  = cell / (POOL * POOL);
    const int rem  = cell - roi * (POOL * POOL);
    const int py   = rem / POOL;
    const int px   = rem - py * POOL;

    const int x = rois[roi * 4 + 0];
    const int y = rois[roi * 4 + 1];
    const int w = rois[roi * 4 + 2];
    const int h = rois[roi * 4 + 3];

    const float hf = (float)h;
    const float wf = (float)w;

    // half-pixel-center source coords, clamped (matches tf.image.resize bilinear)
    float ys = ((float)py + 0.5f) * hf * (1.0f / POOL) - 0.5f;
    float xs = ((float)px + 0.5f) * wf * (1.0f / POOL) - 0.5f;
    ys = fminf(fmaxf(ys, 0.0f), hf - 1.0f);
    xs = fminf(fmaxf(xs, 0.0f), wf - 1.0f);

    const int y0 = (int)floorf(ys);
    const int x0 = (int)floorf(xs);
    const int y1 = min(y0 + 1, h - 1);
    const int x1 = min(x0 + 1, w - 1);
    const float fy = ys - (float)y0;
    const float fx = xs - (float)x0;

    const int ay0 = y + y0, ay1 = y + y1;
    const int ax0 = x + x0, ax1 = x + x1;

    const float4* p00 = (const float4*)(img + ((size_t)(ay0 * IMG_W + ax0)) * CH);
    const float4* p01 = (const float4*)(img + ((size_t)(ay0 * IMG_W + ax1)) * CH);
    const float4* p10 = (const float4*)(img + ((size_t)(ay1 * IMG_W + ax0)) * CH);
    const float4* p11 = (const float4*)(img + ((size_t)(ay1 * IMG_W + ax1)) * CH);

    const float w00 = (1.0f - fy) * (1.0f - fx);
    const float w01 = (1.0f - fy) * fx;
    const float w10 = fy * (1.0f - fx);
    const float w11 = fy * fx;

    const int i0 = lane * 2;
    const int i1 = i0 + 1;

    // 8 independent loads in flight before any dependent math
    float4 a0 = __ldg(p00 + i0);
    float4 a1 = __ldg(p00 + i1);
    float4 b0 = __ldg(p01 + i0);
    float4 b1 = __ldg(p01 + i1);
    float4 c0 = __ldg(p10 + i0);
    float4 c1 = __ldg(p10 + i1);
    float4 d0 = __ldg(p11 + i0);
    float4 d1 = __ldg(p11 + i1);

    float4 r0, r1;
    r0.x = a0.x * w00 + b0.x * w01 + c0.x * w10 + d0.x * w11;
    r0.y = a0.y * w00 + b0.y * w01 + c0.y * w10 + d0.y * w11;
    r0.z = a0.z * w00 + b0.z * w01 + c0.z * w10 + d0.z * w11;
    r0.w = a0.w * w00 + b0.w * w01 + c0.w * w10 + d0.w * w11;
    r1.x = a1.x * w00 + b1.x * w01 + c1.x * w10 + d1.x * w11;
    r1.y = a1.y * w00 + b1.y * w01 + c1.y * w10 + d1.y * w11;
    r1.z = a1.z * w00 + b1.z * w01 + c1.z * w10 + d1.z * w11;
    r1.w = a1.w * w00 + b1.w * w01 + c1.w * w10 + d1.w * w11;

    // streaming stores: don't let the 103MB output evict the 64MB image from L2
    float4* o = (float4*)(out + (size_t)cell * CH);
    __stcs(o + i0, r0);
    __stcs(o + i1, r1);
}

extern "C" void kernel_launch(void* const* d_in, const int* in_sizes, int n_in,
                              void* d_out, int out_size) {
    const float* img  = (const float*)d_in[0];
    const int*   rois = (const int*)d_in[1];
    float*       out  = (float*)d_out;

    const int n_cells = NUM_ROIS * POOL * POOL;   // 25088
    roi_pool_kernel<<<n_cells / 2, 256>>>(img, rois, out);
}

// round 3
// speedup vs baseline: 1.2296x; 1.2296x over previous
#include <cuda_runtime.h>
#include <cstdint>

#define POOL 7
#define NUM_ROIS 512
#define IMG_H 128
#define IMG_W 128
#define CH 1024

// 2 cells per 256-thread block: threads 0-127 -> cell0, 128-255 -> cell1.
// Each thread handles float4 indices lane and lane+128 (both warp-coalesced),
// giving 8 outstanding 16B loads per thread with no wavefront inflation.
__global__ __launch_bounds__(256, 8)
void roi_pool_kernel(const float* __restrict__ img,
                     const int* __restrict__ rois,
                     float* __restrict__ out) {
    const int half = threadIdx.x >> 7;        // 0 or 1
    const int lane = threadIdx.x & 127;       // 0..127
    const int cell = blockIdx.x * 2 + half;   // roi*49 + py*7 + px

    const int roi  = cell / (POOL * POOL);
    const int rem  = cell - roi * (POOL * POOL);
    const int py   = rem / POOL;
    const int px   = rem - py * POOL;

    const int x = rois[roi * 4 + 0];
    const int y = rois[roi * 4 + 1];
    const int w = rois[roi * 4 + 2];
    const int h = rois[roi * 4 + 3];

    const float hf = (float)h;
    const float wf = (float)w;

    // half-pixel-center source coords, clamped (matches tf.image.resize bilinear)
    float ys = ((float)py + 0.5f) * hf * (1.0f / POOL) - 0.5f;
    float xs = ((float)px + 0.5f) * wf * (1.0f / POOL) - 0.5f;
    ys = fminf(fmaxf(ys, 0.0f), hf - 1.0f);
    xs = fminf(fmaxf(xs, 0.0f), wf - 1.0f);

    const int y0 = (int)floorf(ys);
    const int x0 = (int)floorf(xs);
    const int y1 = min(y0 + 1, h - 1);
    const int x1 = min(x0 + 1, w - 1);
    const float fy = ys - (float)y0;
    const float fx = xs - (float)x0;

    const int ay0 = y + y0, ay1 = y + y1;
    const int ax0 = x + x0, ax1 = x + x1;

    const float4* p00 = (const float4*)(img + ((size_t)(ay0 * IMG_W + ax0)) * CH);
    const float4* p01 = (const float4*)(img + ((size_t)(ay0 * IMG_W + ax1)) * CH);
    const float4* p10 = (const float4*)(img + ((size_t)(ay1 * IMG_W + ax0)) * CH);
    const float4* p11 = (const float4*)(img + ((size_t)(ay1 * IMG_W + ax1)) * CH);

    const float w00 = (1.0f - fy) * (1.0f - fx);
    const float w01 = (1.0f - fy) * fx;
    const float w10 = fy * (1.0f - fx);
    const float w11 = fy * fx;

    const int i0 = lane;          // coalesced: warp covers 512B contiguous
    const int i1 = lane + 128;    // coalesced: warp covers 512B contiguous

    // 8 independent loads in flight before any dependent math
    float4 a0 = __ldg(p00 + i0);
    float4 b0 = __ldg(p01 + i0);
    float4 c0 = __ldg(p10 + i0);
    float4 d0 = __ldg(p11 + i0);
    float4 a1 = __ldg(p00 + i1);
    float4 b1 = __ldg(p01 + i1);
    float4 c1 = __ldg(p10 + i1);
    float4 d1 = __ldg(p11 + i1);

    float4 r0, r1;
    r0.x = a0.x * w00 + b0.x * w01 + c0.x * w10 + d0.x * w11;
    r0.y = a0.y * w00 + b0.y * w01 + c0.y * w10 + d0.y * w11;
    r0.z = a0.z * w00 + b0.z * w01 + c0.z * w10 + d0.z * w11;
    r0.w = a0.w * w00 + b0.w * w01 + c0.w * w10 + d0.w * w11;
    r1.x = a1.x * w00 + b1.x * w01 + c1.x * w10 + d1.x * w11;
    r1.y = a1.y * w00 + b1.y * w01 + c1.y * w10 + d1.y * w11;
    r1.z = a1.z * w00 + b1.z * w01 + c1.z * w10 + d1.z * w11;
    r1.w = a1.w * w00 + b1.w * w01 + c1.w * w10 + d1.w * w11;

    // streaming stores: don't let the 103MB output evict the 64MB image from L2
    float4* o = (float4*)(out + (size_t)cell * CH);
    __stcs(o + i0, r0);
    __stcs(o + i1, r1);
}

extern "C" void kernel_launch(void* const* d_in, const int* in_sizes, int n_in,
                              void* d_out, int out_size) {
    const float* img  = (const float*)d_in[0];
    const int*   rois = (const int*)d_in[1];
    float*       out  = (float*)d_out;

    const int n_cells = NUM_ROIS * POOL * POOL;   // 25088
    roi_pool_kernel<<<n_cells / 2, 256>>>(img, rois, out);
}